// round 16
// baseline (speedup 1.0000x reference)
#include <cuda_runtime.h>
#include <cuda_fp16.h>
#include <cstdint>

#define BB 32
#define CC 64
#define HH 64
#define WW 64
#define EE 8
#define HWC (HH*WW)

// Scratch (device globals: no allocation allowed)
__device__ float g_S[BB * 9 * CC];   // box sums [(b*9+k)*64+c], k=di*3+dj
__device__ float g_val[BB];
__device__ int   g_idx[BB];
__device__ __align__(16) uint2 g_x16[BB * CC * HWC / 4];  // fp16 x, word = f16x2 pair

// ===========================================================================
// helpers
// ===========================================================================
__device__ __forceinline__ uint32_t smem_u32(const void* p) {
    uint32_t a;
    asm("{ .reg .u64 t; cvta.to.shared.u64 t, %1; cvt.u32.u64 %0, t; }" : "=r"(a) : "l"(p));
    return a;
}

__device__ __forceinline__ uint32_t pack_f16x2(float even, float odd) {
    __half2 h = __floats2half2_rn(even, odd);
    return *reinterpret_cast<uint32_t*>(&h);
}

#define LDMATRIX_X4(R, addr) \
    asm volatile("ldmatrix.sync.aligned.m8n8.x4.shared.b16 {%0,%1,%2,%3}, [%4];" \
        : "=r"((R)[0]), "=r"((R)[1]), "=r"((R)[2]), "=r"((R)[3]) : "r"(addr))

#define LDMATRIX_X2T(R, addr) \
    asm volatile("ldmatrix.sync.aligned.m8n8.x2.trans.shared.b16 {%0,%1}, [%2];" \
        : "=r"((R)[0]), "=r"((R)[1]) : "r"(addr))

#define MMA_F16(D, A, B0, B1) \
    asm volatile("mma.sync.aligned.m16n8k16.row.col.f32.f16.f16.f32 " \
        "{%0,%1,%2,%3}, {%4,%5,%6,%7}, {%8,%9}, {%0,%1,%2,%3};" \
        : "+f"((D)[0]), "+f"((D)[1]), "+f"((D)[2]), "+f"((D)[3]) \
        : "r"((A)[0]), "r"((A)[1]), "r"((A)[2]), "r"((A)[3]), "r"(B0), "r"(B1))

// ===========================================================================
// Kernel 1: box sums + fp16 conversion write (R11-measured ~11.7us).
// Block = one (b,c) image; 256 threads; float4 at i*256+tid (coalesced).
// ===========================================================================
__global__ __launch_bounds__(256) void region_convert_kernel(const float* __restrict__ x) {
    const int tid = threadIdx.x;
    const float4* base = (const float4*)(x + (size_t)blockIdx.x * HWC);
    float4 v[4];
    #pragma unroll
    for (int i = 0; i < 4; i++) v[i] = base[i * 256 + tid];

    // ---- fp16 conversion write (L2-resident for kernel 3) ----
    uint2* xout = g_x16 + (size_t)blockIdx.x * (HWC / 4);
    #pragma unroll
    for (int i = 0; i < 4; i++) {
        uint2 w;
        w.x = pack_f16x2(v[i].x, v[i].y);
        w.y = pack_f16x2(v[i].z, v[i].w);
        __stcg(xout + i * 256 + tid, w);
    }

    const int g  = tid >> 4;   // 0..15 ; rows touched = i*16 + g
    const int c4 = tid & 15;   // float4 within row

    __shared__ float sRow[4][16];  // partial sums of edge rows 0,1,62,63
    __shared__ float sRE[4][4];    // edge row elems: x[r][0],[1],[62],[63]
    __shared__ float sCol[4][16];  // per-g partials of cols 0,1,62,63
    __shared__ float sG[8];        // per-warp grand totals

    float ps[4], gsum = 0.f;
    #pragma unroll
    for (int i = 0; i < 4; i++) {
        ps[i] = (v[i].x + v[i].y) + (v[i].z + v[i].w);
        gsum += ps[i];
    }
    if (g == 0)  sRow[0][c4] = ps[0];
    if (g == 1)  sRow[1][c4] = ps[0];
    if (g == 14) sRow[2][c4] = ps[3];
    if (g == 15) sRow[3][c4] = ps[3];
    if (c4 == 0) {
        sCol[0][g] = (v[0].x + v[1].x) + (v[2].x + v[3].x);
        sCol[1][g] = (v[0].y + v[1].y) + (v[2].y + v[3].y);
        if (g == 0)  { sRE[0][0] = v[0].x; sRE[0][1] = v[0].y; }
        if (g == 1)  { sRE[1][0] = v[0].x; sRE[1][1] = v[0].y; }
        if (g == 14) { sRE[2][0] = v[3].x; sRE[2][1] = v[3].y; }
        if (g == 15) { sRE[3][0] = v[3].x; sRE[3][1] = v[3].y; }
    }
    if (c4 == 15) {
        sCol[2][g] = (v[0].z + v[1].z) + (v[2].z + v[3].z);
        sCol[3][g] = (v[0].w + v[1].w) + (v[2].w + v[3].w);
        if (g == 0)  { sRE[0][2] = v[0].z; sRE[0][3] = v[0].w; }
        if (g == 1)  { sRE[1][2] = v[0].z; sRE[1][3] = v[0].w; }
        if (g == 14) { sRE[2][2] = v[3].z; sRE[2][3] = v[3].w; }
        if (g == 15) { sRE[3][2] = v[3].z; sRE[3][3] = v[3].w; }
    }
    #pragma unroll
    for (int o = 16; o; o >>= 1) gsum += __shfl_xor_sync(0xffffffffu, gsum, o);
    if ((tid & 31) == 0) sG[tid >> 5] = gsum;
    __syncthreads();

    if (tid < 9) {
        int di = tid / 3, dj = tid - di * 3;
        float G = 0.f;
        #pragma unroll
        for (int j = 0; j < 8; j++) G += sG[j];
        float c0 = 0.f, c1 = 0.f, c62 = 0.f, c63 = 0.f;
        #pragma unroll
        for (int j = 0; j < 16; j++) {
            c0 += sCol[0][j]; c1 += sCol[1][j]; c62 += sCol[2][j]; c63 += sCol[3][j];
        }
        float colc = (dj == 0) ? (c62 + c63) : (dj == 1) ? (c0 + c63) : (c0 + c1);
        float T = G - colc;                 // sum of cv_dj over all 64 rows
        float rw[4];
        #pragma unroll
        for (int er = 0; er < 4; er++) {
            float s = 0.f;
            #pragma unroll
            for (int j = 0; j < 16; j++) s += sRow[er][j];
            float ec = (dj == 0) ? (sRE[er][2] + sRE[er][3])
                     : (dj == 1) ? (sRE[er][0] + sRE[er][3])
                                 : (sRE[er][0] + sRE[er][1]);
            rw[er] = s - ec;                // cv_dj of that edge row
        }
        float sub = (di == 0) ? (rw[2] + rw[3])
                  : (di == 1) ? (rw[0] + rw[3])
                              : (rw[0] + rw[1]);
        int b = blockIdx.x >> 6, c = blockIdx.x & 63;
        g_S[(b * 9 + tid) * CC + c] = T - sub;
    }
}

// ===========================================================================
// Kernel 2: gate (32 blocks; smem-staged g_S).
// ===========================================================================
__global__ __launch_bounds__(256) void gate_kernel(const float* __restrict__ gate_w,
                                                   const float* __restrict__ gate_b,
                                                   float* __restrict__ ew_out,
                                                   int write_ew) {
    int b = blockIdx.x;
    int tid = threadIdx.x;
    __shared__ float Ssh[9 * 64];
    __shared__ float gat[8];

    for (int i = tid; i < 576; i += 256) Ssh[i] = g_S[b*576 + i];
    __syncthreads();

    int warp = tid >> 5, lane = tid & 31;  // warp = expert
    float acc = 0.f;
    for (int idx = lane; idx < 576; idx += 32) {
        int c = idx / 9;
        int k = idx - c * 9;
        acc += gate_w[warp * 576 + idx] * Ssh[k * 64 + c];
    }
    #pragma unroll
    for (int o = 16; o; o >>= 1) acc += __shfl_down_sync(0xffffffffu, acc, o);
    if (lane == 0) gat[warp] = acc + gate_b[warp] * 3844.0f;  // 62*62 positions
    __syncthreads();

    if (tid == 0) {
        float m = gat[0]; int mi = 0;
        #pragma unroll
        for (int e = 1; e < 8; e++) { if (gat[e] > m) { m = gat[e]; mi = e; } }
        float s = 0.f;
        #pragma unroll
        for (int e = 0; e < 8; e++) s += expf(gat[e] - m);
        g_val[b] = 1.0f / s;
        g_idx[b] = mi;
    }
    __syncthreads();
    if (write_ew && tid < 8) {
        ew_out[b * 8 + tid] = (tid == g_idx[b]) ? g_val[b] : 0.0f;
    }
}

// ===========================================================================
// Kernel 3: fp16 mma.sync GEMM reading the fp16 side-buffer.
//   X stage: pure copy g_x16 -> smem (4 LDG.128 + 4 STS.128/thread, no ALU).
//   W stage: coalesced fp16 tile + ldmatrix.x4 fragments (R15 win).
//   Epilogue: direct __stcs streaming stores.
// Block 256 thr (8 warps: wf=warp>>1 16f, wn=warp&1 64hw); tile 64f x 128hw.
// ===========================================================================
#define WPITCH 36u   // words per W row (32 data words + 4 pad) -> 144B row pitch
#define XPITCH 68u   // words per X row (64 data words + 4 pad)

__global__ __launch_bounds__(256) void gemm_kernel(const float* __restrict__ expert_w,
                                                   float* __restrict__ out) {
    __shared__ uint32_t sW[64 * WPITCH];   // 9.2 KB fp16x2 W tile [f][c-pairs]
    __shared__ uint32_t sX[64 * XPITCH];   // 17.4 KB fp16x2 X tile [c][hw-pairs]
    __shared__ float shv;
    __shared__ int   she;

    const int tid   = threadIdx.x;
    const int warp  = tid >> 5, lane = tid & 31;
    const int chunk = blockIdx.x;
    const int b     = blockIdx.y;
    const int hw0   = chunk * 128;

    if (tid == 0) { shv = g_val[b]; she = g_idx[b]; }
    __syncthreads();
    const int e = she;

    // ---- stage W: coalesced gmem read (L2-hot 16KB), fp16 convert ----
    {
        const float4* Wb4 = (const float4*)(expert_w + (size_t)e * 4096);
        #pragma unroll
        for (int i = 0; i < 4; i++) {
            int p = tid + i * 256;          // float4 index 0..1023
            int f = p >> 4, q = p & 15;     // 16 float4 per 64-float row
            float4 w = Wb4[p];
            sW[f * WPITCH + q * 2]     = pack_f16x2(w.x, w.y);
            sW[f * WPITCH + q * 2 + 1] = pack_f16x2(w.z, w.w);
        }
    }

    // ---- stage X: pure copy from fp16 side-buffer (L2-hot) ----
    {
        const uint4* xs4 = (const uint4*)(g_x16 + ((size_t)b * CC * HWC + hw0) / 4);
        #pragma unroll
        for (int i = 0; i < 4; i++) {
            int p = tid + i * 256;          // uint4 index 0..1023
            int c = p >> 4, q = p & 15;     // 16 uint4 per row (64 words)
            uint4 w = __ldcg(xs4 + (size_t)c * (HWC / 8) + q);
            *(uint4*)(sX + c * XPITCH + q * 4) = w;
        }
    }
    __syncthreads();
    const float val = shv;

    // ---- A fragments via ldmatrix.x4 ----
    const int wf = warp >> 1;   // 0..3 : 16 f rows each
    const int wn = warp & 1;    // 0..1 : 64 hw cols each
    const uint32_t swb = smem_u32(sW);
    uint32_t af[4][4];
    {
        uint32_t rowsel = (uint32_t)(lane & 15);
        uint32_t seg    = (uint32_t)(lane >> 4) * 16u;   // k +8 halves
        uint32_t row    = (uint32_t)(wf * 16) + rowsel;
        #pragma unroll
        for (int kt = 0; kt < 4; kt++) {
            uint32_t off = row * (WPITCH * 4u) + (uint32_t)kt * 32u + seg;
            LDMATRIX_X4(af[kt], swb + off);
        }
    }

    float acc[8][4];
    #pragma unroll
    for (int nt = 0; nt < 8; nt++)
        #pragma unroll
        for (int q = 0; q < 4; q++) acc[nt][q] = 0.f;

    const uint32_t sxb = smem_u32(sX);
    const uint32_t krow = (uint32_t)(lane & 15);
    #pragma unroll
    for (int kt = 0; kt < 4; kt++) {
        uint32_t kbase = ((uint32_t)(kt * 16) + krow) * (XPITCH * 4u);
        #pragma unroll
        for (int nt = 0; nt < 8; nt++) {
            uint32_t noff = (uint32_t)(wn * 64 + nt * 8) * 2u;
            uint32_t bf[2];
            LDMATRIX_X2T(bf, sxb + kbase + noff);
            MMA_F16(acc[nt], af[kt], bf[0], bf[1]);
        }
    }

    // ---- epilogue: streaming stores ----
    float* outb = out + (size_t)b * CC * HWC + hw0;
    int f0 = wf * 16 + (lane >> 2);
    int cbase = wn * 64 + (lane & 3) * 2;
    #pragma unroll
    for (int nt = 0; nt < 8; nt++) {
        int cc = cbase + nt * 8;
        float2 v0 = make_float2(acc[nt][0] * val, acc[nt][1] * val);
        float2 v1 = make_float2(acc[nt][2] * val, acc[nt][3] * val);
        __stcs((float2*)(outb + (size_t)f0 * HWC + cc),       v0);
        __stcs((float2*)(outb + (size_t)(f0 + 8) * HWC + cc), v1);
    }
}

// ===========================================================================
extern "C" void kernel_launch(void* const* d_in, const int* in_sizes, int n_in,
                              void* d_out, int out_size) {
    const float* x = nullptr, *gate_w = nullptr, *gate_b = nullptr, *expert_w = nullptr;
    for (int i = 0; i < n_in; i++) {
        switch (in_sizes[i]) {
            case BB*CC*HH*WW: x        = (const float*)d_in[i]; break;  // 524288
            case EE*CC*3*3:   gate_w   = (const float*)d_in[i]; break;  // 4608
            case EE:          gate_b   = (const float*)d_in[i]; break;  // 8
            case EE*CC*CC:    expert_w = (const float*)d_in[i]; break;  // 32768
            default: break;
        }
    }
    float* out = (float*)d_out;
    const int main_elems = BB * CC * HWC;
    int write_ew = (out_size >= main_elems + BB * EE) ? 1 : 0;

    region_convert_kernel<<<BB * CC, 256>>>(x);
    gate_kernel<<<BB, 256>>>(gate_w, gate_b, out + main_elems, write_ew);
    gemm_kernel<<<dim3(HWC / 128, BB), 256>>>(expert_w, out);
}